// round 7
// baseline (speedup 1.0000x reference)
#include <cuda_runtime.h>

// DisplacementVectorsASU — gather + per-edge affine transform.
//
// Inputs (metadata order):
//   d_in[0] frac_coords       float32  (100000, 3)
//   d_in[1] edge_indices      int32    (2, 4000000)
//   d_in[2] symmops           float32  (4000000, 4, 4)
//   d_in[3] cell_translations float32  (4000000, 3)
// Output: float32 (4000000, 3)
//
// R7 design (evidence so far):
//  - float4 node table, 1 LDG per gather (R3); default cache policy (R4:
//    evict hints +24us); front-batched MLP beats occupancy (R5 vs R6).
//  - NEW: all long-latency loads issued as cp.async (LDGSTS) into smem:
//    gathers, symmop rows, cell_translations. No destination registers are
//    held, so 4 edges/thread (8 in-flight gathers) fit in ~36 regs. One
//    wait_group 0 + syncthreads, then a pure-smem compute phase.
//  - smem regions are slot-per-edge (16B stride) -> conflict-free LDS.128.
//  - output staged in smem (aliases gather region after sync), stored as
//    coalesced float4.

#define NODE_CAP 131072
__device__ float4 g_frac4[NODE_CAP];

__global__ __launch_bounds__(512)
void pack_frac_kernel(const float* __restrict__ frac, int n)
{
    int i = blockIdx.x * blockDim.x + threadIdx.x;
    if (i < n) {
        float4 v;
        v.x = __ldg(frac + 3 * i + 0);
        v.y = __ldg(frac + 3 * i + 1);
        v.z = __ldg(frac + 3 * i + 2);
        v.w = 0.0f;
        g_frac4[i] = v;
    }
}

#define TPB 128
#define EPT 4
#define EPB 512   // TPB * EPT

__device__ __forceinline__ unsigned smem_u32(const void* p)
{
    unsigned a;
    asm("{ .reg .u64 t; cvta.to.shared.u64 t, %1; cvt.u32.u64 %0, t; }"
        : "=r"(a) : "l"(p));
    return a;
}

__device__ __forceinline__ void cp16(unsigned dst, const void* src)
{
    asm volatile("cp.async.ca.shared.global [%0], [%1], 16;"
                 :: "r"(dst), "l"(src));
}

__global__ __launch_bounds__(TPB)
void displacement_kernel(const int*    __restrict__ ei,
                         const float*  __restrict__ sym,   // 16 floats per edge
                         const float4* __restrict__ ct4,
                         float4*       __restrict__ out4,
                         int M)
{
    // Regions, slot-per-local-edge (16B stride => conflict-free LDS.128):
    __shared__ float4 s_fin[EPB];        // 8KB  (reused as s_out after sync)
    __shared__ float4 s_fo [EPB];        // 8KB
    __shared__ float4 s_r0 [EPB];        // 8KB
    __shared__ float4 s_r1 [EPB];        // 8KB
    __shared__ float4 s_r2 [EPB];        // 8KB
    __shared__ float  s_ct [EPB * 3];    // 6KB
    float* s_out = (float*)s_fin;        // 6KB alias, used after barrier

    const int tid       = threadIdx.x;
    const int blockBase = blockIdx.x * EPB;

    const unsigned a_fin = smem_u32(s_fin);
    const unsigned a_fo  = smem_u32(s_fo);
    const unsigned a_r0  = smem_u32(s_r0);
    const unsigned a_r1  = smem_u32(s_r1);
    const unsigned a_r2  = smem_u32(s_r2);
    const unsigned a_ct  = smem_u32(s_ct);

    // ---- issue phase: everything async, nothing blocks ----
    int eidx[EPT];
    bool val[EPT];
    #pragma unroll
    for (int k = 0; k < EPT; k++) {
        const int lt = tid + k * TPB;          // local edge slot
        const int e  = blockBase + lt;
        eidx[k] = e;
        val[k]  = (e < M);
        if (val[k]) {
            const int i0 = __ldg(ei + e);      // in-node
            const int i1 = __ldg(ei + M + e);  // out-node
            cp16(a_fin + lt * 16, g_frac4 + i0);
            cp16(a_fo  + lt * 16, g_frac4 + i1);
            const float* sb = sym + 16L * e;   // rows 0..2 only (48B of 64B)
            cp16(a_r0 + lt * 16, sb + 0);
            cp16(a_r1 + lt * 16, sb + 4);
            cp16(a_r2 + lt * 16, sb + 8);
        }
    }
    // cell_translations: 384 float4 per block, coalesced async copies
    {
        const long f4base = (long)blockBase * 3 / 4;
        #pragma unroll
        for (int i = tid; i < EPB * 3 / 4; i += TPB) {
            if ((f4base + i) * 4 < (long)M * 3)
                cp16(a_ct + i * 16, ct4 + f4base + i);
        }
    }
    asm volatile("cp.async.commit_group;" ::: "memory");
    asm volatile("cp.async.wait_group 0;" ::: "memory");
    __syncthreads();

    // ---- compute phase: pure smem -> 12 result floats in registers ----
    float res[EPT][3];
    #pragma unroll
    for (int k = 0; k < EPT; k++) {
        if (val[k]) {
            const int lt = tid + k * TPB;
            const float4 fo = s_fo[lt];
            const float4 r0 = s_r0[lt];
            const float4 r1 = s_r1[lt];
            const float4 r2 = s_r2[lt];
            const float4 fi = s_fin[lt];
            float t0 = fmaf(r0.x, fo.x, fmaf(r0.y, fo.y, fmaf(r0.z, fo.z, r0.w)));
            float t1 = fmaf(r1.x, fo.x, fmaf(r1.y, fo.y, fmaf(r1.z, fo.z, r1.w)));
            float t2 = fmaf(r2.x, fo.x, fmaf(r2.y, fo.y, fmaf(r2.z, fo.z, r2.w)));
            res[k][0] = fi.x - (t0 - floorf(t0) + s_ct[3 * lt + 0]);
            res[k][1] = fi.y - (t1 - floorf(t1) + s_ct[3 * lt + 1]);
            res[k][2] = fi.z - (t2 - floorf(t2) + s_ct[3 * lt + 2]);
        }
    }
    __syncthreads();   // all gather-region reads done before aliasing as s_out

    #pragma unroll
    for (int k = 0; k < EPT; k++) {
        if (val[k]) {
            const int lt = tid + k * TPB;
            s_out[3 * lt + 0] = res[k][0];
            s_out[3 * lt + 1] = res[k][1];
            s_out[3 * lt + 2] = res[k][2];
        }
    }
    __syncthreads();

    // ---- coalesced float4 store of the output ----
    {
        const long f4base = (long)blockBase * 3 / 4;
        #pragma unroll
        for (int i = tid; i < EPB * 3 / 4; i += TPB) {
            long idx = f4base + i;
            if (idx * 4 < (long)M * 3)
                out4[idx] = ((const float4*)s_out)[i];
        }
    }
}

extern "C" void kernel_launch(void* const* d_in, const int* in_sizes, int n_in,
                              void* d_out, int out_size)
{
    const float*  frac = (const float*) d_in[0];
    const int*    ei   = (const int*)   d_in[1];
    const float*  sym  = (const float*) d_in[2];
    const float4* ct4  = (const float4*)d_in[3];
    float4*       out4 = (float4*)      d_out;

    const int n = in_sizes[0] / 3;      // node count
    const int M = in_sizes[1] / 2;      // edge count

    pack_frac_kernel<<<(n + 511) / 512, 512>>>(frac, n);

    const int blocks = (M + EPB - 1) / EPB;
    displacement_kernel<<<blocks, TPB>>>(ei, sym, ct4, out4, M);
}